// round 7
// baseline (speedup 1.0000x reference)
#include <cuda_runtime.h>
#include <math.h>

#define BDIM 16
#define CO   64
#define RN   24            // Chebyshev nodes
#define CC   72            // padded channels: [0..63]=co, [64]=density, [65..71]=pad
#define RDIM 128

// ---------------- device globals (scratch) ----------------
__device__ unsigned g_lo_u, g_hi_u;
__device__ __align__(16) float g_s[RN];
__device__ __align__(16) float g_w[RN];
__device__ float g_a;
__device__ __align__(16) float g_K[RN * RN];
__device__ __align__(16) float g_A[BDIM * RN * CC];      // atomically accumulated
__device__ __align__(16) float g_Btd[BDIM * RN];
__device__ __align__(16) float g_WB[BDIM * RN * RDIM];

__device__ __forceinline__ unsigned f2ord(float f) {
    unsigned u = __float_as_uint(f);
    return (u & 0x80000000u) ? ~u : (u | 0x80000000u);
}
__device__ __forceinline__ float ord2f(unsigned u) {
    return (u & 0x80000000u) ? __uint_as_float(u ^ 0x80000000u) : __uint_as_float(~u);
}

// ---------------- kernel 1: min/max over ci and ti ----------------
__global__ void k_minmax(const float* __restrict__ ci, const float* __restrict__ ti,
                         int nci, int nti) {
    int total = nci + nti;
    float lo = 3.4e38f, hi = -3.4e38f;
    for (int i = blockIdx.x * blockDim.x + threadIdx.x; i < total;
         i += gridDim.x * blockDim.x) {
        float v = (i < nci) ? ci[i] : ti[i - nci];
        lo = fminf(lo, v);
        hi = fmaxf(hi, v);
    }
    #pragma unroll
    for (int o = 16; o; o >>= 1) {
        lo = fminf(lo, __shfl_xor_sync(0xFFFFFFFFu, lo, o));
        hi = fmaxf(hi, __shfl_xor_sync(0xFFFFFFFFu, hi, o));
    }
    if ((threadIdx.x & 31) == 0) {
        atomicMin(&g_lo_u, f2ord(lo));
        atomicMax(&g_hi_u, f2ord(hi));
    }
}

// ---------------- kernel 2: nodes + weights + node-pair kernel matrix ----------------
__global__ void k_setup(const float* __restrict__ ls) {
    __shared__ float ss[RN];
    int tid = threadIdx.x;
    if (tid == 0) {
        float l = ls[0];
        g_a = -0.5f / (l * l);
    }
    if (tid < RN) {
        float lo = ord2f(g_lo_u), hi = ord2f(g_hi_u);
        float c = 0.5f * (lo + hi);
        float h = 0.5f * (hi - lo) * 1.0002f + 1e-5f;
        double ang = (double)tid * M_PI / (double)(RN - 1);
        float s = c + h * (float)cos(ang);
        g_s[tid] = s;
        ss[tid] = s;
        float wj = ((tid == 0) || (tid == RN - 1)) ? 0.5f : 1.0f;
        g_w[tid] = (tid & 1) ? -wj : wj;
    }
    __syncthreads();
    for (int i = tid; i < RN * RN; i += blockDim.x) {
        int p = i / RN, q = i - p * RN;
        float d = ss[p] - ss[q];
        g_K[i] = expf(g_a * d * d);
    }
}

// ---------------- kernel 3: stage A  g_A[b,q,cc] += sum_n L_q(ci_n)*co (atomic) ----------------
#define SA_LT    0                          // Lt[24][129] = 3096
#define SA_CO    3096                       // co_s[128][72] = 9216
#define SA_INVD  12312                      // invd[128]
#define SA_S     12440
#define SA_W     (SA_S + RN)
#define SA_FLOATS (SA_W + RN)               // 12488 floats = 49952 B

__global__ void __launch_bounds__(256)
k_stageA(const float* __restrict__ ci, const float* __restrict__ co) {
    extern __shared__ float sm[];
    float* Lt   = sm + SA_LT;
    float* co_s = sm + SA_CO;
    float* invd = sm + SA_INVD;
    float* s_s  = sm + SA_S;
    float* w_s  = sm + SA_W;

    const int tid = threadIdx.x;
    const int chunk = blockIdx.x, b = blockIdx.y;
    const int n0 = chunk * 256;

    if (tid < RN) { s_s[tid] = g_s[tid]; w_s[tid] = g_w[tid]; }
    __syncthreads();

    const int g = tid / 24, q = tid - g * 24;   // active when tid < 216: g 0..8, q 0..23
    const bool act = (tid < 216);
    float4 acc0 = make_float4(0.f, 0.f, 0.f, 0.f);
    float4 acc1 = make_float4(0.f, 0.f, 0.f, 0.f);

    for (int sub = 0; sub < 2; ++sub) {
        const int nb = n0 + sub * 128;
        __syncthreads();
        if (tid < 128) {
            float x = ci[(nb + tid) * BDIM + b];
            float den = 0.0f;
            #pragma unroll 8
            for (int j = 0; j < RN; ++j) {
                float d = x - s_s[j];
                if (d == 0.0f) d = 1e-30f;
                float r = __fdividef(w_s[j], d);
                den += r;
                Lt[j * 129 + tid] = r;
            }
            invd[tid] = __fdividef(1.0f, den);
        } else {
            for (int i = tid - 128; i < 128 * 18; i += 128) {
                int nn = i / 18, c4 = i - nn * 18;
                float4 v;
                if (c4 < 16)
                    v = ((const float4*)(co + ((size_t)(nb + nn) * BDIM + b) * CO))[c4];
                else if (c4 == 16)
                    v = make_float4(1.f, 0.f, 0.f, 0.f);
                else
                    v = make_float4(0.f, 0.f, 0.f, 0.f);
                ((float4*)co_s)[nn * 18 + c4] = v;
            }
        }
        __syncthreads();

        if (act) {
            const float4* co4 = (const float4*)co_s;
            #pragma unroll 4
            for (int n = 0; n < 128; ++n) {
                float k = Lt[q * 129 + n] * invd[n];
                float4 x0 = co4[n * 18 + g * 2];
                float4 x1 = co4[n * 18 + g * 2 + 1];
                acc0.x = fmaf(k, x0.x, acc0.x); acc0.y = fmaf(k, x0.y, acc0.y);
                acc0.z = fmaf(k, x0.z, acc0.z); acc0.w = fmaf(k, x0.w, acc0.w);
                acc1.x = fmaf(k, x1.x, acc1.x); acc1.y = fmaf(k, x1.y, acc1.y);
                acc1.z = fmaf(k, x1.z, acc1.z); acc1.w = fmaf(k, x1.w, acc1.w);
            }
        }
    }
    if (act) {
        float* ap = g_A + ((size_t)b * RN + q) * CC + g * 8;
        atomicAdd(ap + 0, acc0.x); atomicAdd(ap + 1, acc0.y);
        atomicAdd(ap + 2, acc0.z); atomicAdd(ap + 3, acc0.w);
        atomicAdd(ap + 4, acc1.x); atomicAdd(ap + 5, acc1.y);
        atomicAdd(ap + 6, acc1.z); atomicAdd(ap + 7, acc1.w);
    }
}

// ---------------- kernel 4: stage B  per (b, 16-r chunk): Bt = K*A ; WB slice = Bt*W^T ----------------
__global__ void __launch_bounds__(128)
k_stageB(const float* __restrict__ W) {
    __shared__ float As[RN * CC];
    __shared__ float Ks[RN * RN];
    __shared__ float Bt[RN * CC];
    __shared__ float Ws[16 * 65];
    const int tid = threadIdx.x, b = blockIdx.x, rc = blockIdx.y;
    const int r0 = rc * 16;

    for (int i = tid; i < RN * CC / 4; i += 128)
        ((float4*)As)[i] = ((const float4*)(g_A + (size_t)b * RN * CC))[i];
    for (int i = tid; i < RN * RN; i += 128) Ks[i] = g_K[i];
    for (int i = tid; i < 16 * 65; i += 128) Ws[i] = W[r0 * 65 + i];
    __syncthreads();

    for (int i = tid; i < RN * CC; i += 128) {
        int p = i / CC, c = i - p * CC;
        float acc = 0.0f;
        #pragma unroll 8
        for (int qq = 0; qq < RN; ++qq)
            acc = fmaf(Ks[p * RN + qq], As[qq * CC + c], acc);
        Bt[i] = acc;
        if (c == 64 && rc == 0) g_Btd[b * RN + p] = acc;
    }
    __syncthreads();

    for (int i = tid; i < RN * 16; i += 128) {
        int p = i >> 4, rr = i & 15;
        float acc = 0.0f;
        #pragma unroll 8
        for (int c = 0; c < 64; ++c)
            acc = fmaf(Ws[rr * 65 + (c + 1)], Bt[p * CC + c], acc);
        g_WB[((size_t)b * RN + p) * RDIM + r0 + rr] = acc;
    }
}

// ---------------- kernel 5: stage C  out = (L^T WB)/dens + W0*dens + bias ----------------
// 128 threads, thread tile 16m x 8r over a 128m x 128r block tile.
#define SC_LAT  0                           // Lat[24][132] = 3168
#define SC_WBS  3168                        // WBs[24][128] = 3072
#define SC_DENS 6240                        // 128
#define SC_BTD  6368
#define SC_S    (SC_BTD + RN)
#define SC_W    (SC_S + RN)
#define SC_W0   (SC_W + RN)
#define SC_BIAS (SC_W0 + 128)
#define SC_FLOATS (SC_BIAS + 128)           // 6696 floats = 26784 B

__global__ void __launch_bounds__(128, 2)
k_stageC(const float* __restrict__ ti, const float* __restrict__ W,
         const float* __restrict__ bias, float* __restrict__ out) {
    extern __shared__ float sm[];
    float* Lat  = sm + SC_LAT;
    float* WBs  = sm + SC_WBS;
    float* dens = sm + SC_DENS;
    float* Btd  = sm + SC_BTD;
    float* s_s  = sm + SC_S;
    float* w_s  = sm + SC_W;
    float* W0s  = sm + SC_W0;
    float* bi_s = sm + SC_BIAS;

    const int tid = threadIdx.x;
    const int m0 = blockIdx.x * 128, b = blockIdx.y;

    for (int i = tid; i < RN * RDIM / 4; i += 128)
        ((float4*)WBs)[i] = ((const float4*)(g_WB + (size_t)b * RN * RDIM))[i];
    if (tid < RN) {
        Btd[tid] = g_Btd[b * RN + tid];
        s_s[tid] = g_s[tid];
        w_s[tid] = g_w[tid];
    }
    W0s[tid]  = W[tid * 65];
    bi_s[tid] = bias[tid];
    __syncthreads();

    {   // every thread: barycentric weights for its m = m0 + tid
        float x = ti[(m0 + tid) * BDIM + b];
        float den = 0.0f;
        #pragma unroll 8
        for (int j = 0; j < RN; ++j) {
            float d = x - s_s[j];
            if (d == 0.0f) d = 1e-30f;
            float r = __fdividef(w_s[j], d);
            den += r;
            Lat[j * 132 + tid] = r;
        }
        float inv = __fdividef(1.0f, den);
        float dm = 0.0f;
        #pragma unroll 8
        for (int j = 0; j < RN; ++j) {
            float v = Lat[j * 132 + tid] * inv;
            Lat[j * 132 + tid] = v;
            dm = fmaf(v, Btd[j], dm);
        }
        dens[tid] = dm;
    }
    __syncthreads();

    const int tx = tid & 7, ty = tid >> 3;   // tx 0..7 (m), ty 0..15 (r)
    const int mi = tx * 16, ri = ty * 8;
    float acc[16][8];
    #pragma unroll
    for (int k = 0; k < 16; ++k)
        #pragma unroll
        for (int j = 0; j < 8; ++j) acc[k][j] = 0.0f;

    const float4* Lat4 = (const float4*)Lat;
    const float4* WBs4 = (const float4*)WBs;
    #pragma unroll 2
    for (int p = 0; p < RN; ++p) {
        float4 a0 = Lat4[p * 33 + tx * 4];
        float4 a1 = Lat4[p * 33 + tx * 4 + 1];
        float4 a2 = Lat4[p * 33 + tx * 4 + 2];
        float4 a3 = Lat4[p * 33 + tx * 4 + 3];
        float4 b0 = WBs4[p * 32 + ty * 2];
        float4 b1 = WBs4[p * 32 + ty * 2 + 1];
        float am[16] = {a0.x, a0.y, a0.z, a0.w, a1.x, a1.y, a1.z, a1.w,
                        a2.x, a2.y, a2.z, a2.w, a3.x, a3.y, a3.z, a3.w};
        float br[8]  = {b0.x, b0.y, b0.z, b0.w, b1.x, b1.y, b1.z, b1.w};
        #pragma unroll
        for (int k = 0; k < 16; ++k)
            #pragma unroll
            for (int j = 0; j < 8; ++j)
                acc[k][j] = fmaf(am[k], br[j], acc[k][j]);
    }

    float w0[8], bi[8];
    #pragma unroll
    for (int j = 0; j < 8; ++j) { w0[j] = W0s[ri + j]; bi[j] = bi_s[ri + j]; }
    #pragma unroll
    for (int k = 0; k < 16; ++k) {
        float dm = dens[mi + k];
        float inv = __fdividef(1.0f, dm + 1e-8f);
        float o[8];
        #pragma unroll
        for (int j = 0; j < 8; ++j)
            o[j] = fmaf(acc[k][j], inv, fmaf(w0[j], dm, bi[j]));
        float* op = out + ((size_t)(m0 + mi + k) * BDIM + b) * RDIM + ri;
        ((float4*)op)[0] = make_float4(o[0], o[1], o[2], o[3]);
        ((float4*)op)[1] = make_float4(o[4], o[5], o[6], o[7]);
    }
}

// ---------------- launch ----------------
extern "C" void kernel_launch(void* const* d_in, const int* in_sizes, int n_in,
                              void* d_out, int out_size)
{
    const float* ci   = (const float*)d_in[0];
    const float* co   = (const float*)d_in[1];
    const float* ti   = (const float*)d_in[2];
    const float* ls   = (const float*)d_in[3];
    const float* W    = (const float*)d_in[4];
    const float* bias = (const float*)d_in[5];
    float* out = (float*)d_out;

    const int N = in_sizes[0] / BDIM;   // 2048
    const int M = in_sizes[2] / BDIM;   // 4096

    cudaFuncSetAttribute(k_stageA, cudaFuncAttributeMaxDynamicSharedMemorySize,
                         SA_FLOATS * 4);
    cudaFuncSetAttribute(k_stageC, cudaFuncAttributeMaxDynamicSharedMemorySize,
                         SC_FLOATS * 4);

    void *p_lo, *p_hi, *p_A;
    cudaGetSymbolAddress(&p_lo, g_lo_u);
    cudaGetSymbolAddress(&p_hi, g_hi_u);
    cudaGetSymbolAddress(&p_A,  g_A);
    cudaMemsetAsync(p_lo, 0xFF, 4);
    cudaMemsetAsync(p_hi, 0x00, 4);
    cudaMemsetAsync(p_A,  0x00, BDIM * RN * CC * sizeof(float));

    k_minmax<<<96, 256>>>(ci, ti, N * BDIM, M * BDIM);
    k_setup<<<1, 1024>>>(ls);
    k_stageA<<<dim3(N / 256, BDIM), 256, SA_FLOATS * 4>>>(ci, co);
    k_stageB<<<dim3(BDIM, RDIM / 16), 128>>>(W);
    k_stageC<<<dim3(M / 128, BDIM), 128, SC_FLOATS * 4>>>(ti, W, bias, out);
}

// round 8
// speedup vs baseline: 1.0714x; 1.0714x over previous
#include <cuda_runtime.h>
#include <math.h>

#define BDIM 16
#define CO   64
#define RN   24            // Chebyshev nodes
#define CC   72            // padded channels: [0..63]=co, [64]=density, [65..71]=pad
#define RDIM 128
#define NBLK 256
#define NTHR 256

// ---------------- device globals ----------------
__device__ unsigned g_lo_u, g_hi_u;
__device__ int g_bar_cnt;
__device__ volatile int g_bar_gen;
__device__ __align__(16) float g_A[BDIM * RN * CC];      // atomically accumulated
__device__ __align__(16) float g_Btd[BDIM * RN];
__device__ __align__(16) float g_WB[BDIM * RN * RDIM];

__device__ __forceinline__ unsigned f2ord(float f) {
    unsigned u = __float_as_uint(f);
    return (u & 0x80000000u) ? ~u : (u | 0x80000000u);
}
__device__ __forceinline__ float ord2f(unsigned u) {
    return (u & 0x80000000u) ? __uint_as_float(u ^ 0x80000000u) : __uint_as_float(~u);
}

// software grid barrier: all NBLK blocks are co-resident by construction
__device__ __forceinline__ void grid_barrier() {
    __syncthreads();
    if (threadIdx.x == 0) {
        __threadfence();
        int gen = g_bar_gen;
        if (atomicAdd(&g_bar_cnt, 1) == NBLK - 1) {
            atomicExch(&g_bar_cnt, 0);
            __threadfence();
            g_bar_gen = gen + 1;
        } else {
            while (g_bar_gen == gen) { __nanosleep(64); }
        }
        __threadfence();
    }
    __syncthreads();
}

// ---------------- smem layout (floats) ----------------
// persistent: s[24] w[24] K[576] misc[8]  -> 632
#define P_S   0
#define P_W   RN                 // 24
#define P_K   (2 * RN)           // 48
#define P_MSC (P_K + RN * RN)    // 624  (0:a, 1:lo, 2:hi)
#define SCR   632                // scratch base (16B aligned: 632*4=2528)
// stage A scratch: Lt[24][129]=3096 @SCR, co_s[128][18f4]=9216 @SCR+3096, invd[128] @SCR+12312
// stage B scratch: As[1728] @SCR, Bt[1728] @SCR+1728, Ws[520] @SCR+3456
// stage C scratch: Lat[24][132]=3168 @SCR, WBs[3072] @SCR+3168, dens[128] @SCR+6240,
//                  Btd[24] @SCR+6368, W0s[128] @SCR+6392, bi[128] @SCR+6520
#define SM_FLOATS (SCR + 12440)  // 13072 floats = 52288 B

__global__ void __launch_bounds__(NTHR, 2)
k_all(const float* __restrict__ ci, const float* __restrict__ co,
      const float* __restrict__ ti, const float* __restrict__ ls,
      const float* __restrict__ W, const float* __restrict__ bias,
      float* __restrict__ out, int N, int M)
{
    extern __shared__ float sm[];
    const int tid = threadIdx.x, bid = blockIdx.x;

    // ================= phase 0: global min/max =================
    {
        const int nci = N * BDIM;
        const int total = nci + M * BDIM;
        float lo = 3.4e38f, hi = -3.4e38f;
        for (int i = bid * NTHR + tid; i < total; i += NBLK * NTHR) {
            float v = (i < nci) ? ci[i] : ti[i - nci];
            lo = fminf(lo, v);
            hi = fmaxf(hi, v);
        }
        #pragma unroll
        for (int o = 16; o; o >>= 1) {
            lo = fminf(lo, __shfl_xor_sync(0xFFFFFFFFu, lo, o));
            hi = fmaxf(hi, __shfl_xor_sync(0xFFFFFFFFu, hi, o));
        }
        if ((tid & 31) == 0) {
            atomicMin(&g_lo_u, f2ord(lo));
            atomicMax(&g_hi_u, f2ord(hi));
        }
    }
    grid_barrier();

    // ================= phase 1: per-block setup (s, w, K in smem) =================
    {
        if (tid == 0) {
            float l = ls[0];
            sm[P_MSC + 0] = -0.5f / (l * l);
            sm[P_MSC + 1] = ord2f(__ldcg(&g_lo_u));
            sm[P_MSC + 2] = ord2f(__ldcg(&g_hi_u));
        }
        __syncthreads();
        if (tid < RN) {
            float lo = sm[P_MSC + 1], hi = sm[P_MSC + 2];
            float c = 0.5f * (lo + hi);
            float h = 0.5f * (hi - lo) * 1.0002f + 1e-5f;
            double ang = (double)tid * M_PI / (double)(RN - 1);
            sm[P_S + tid] = c + h * (float)cos(ang);
            float wj = ((tid == 0) || (tid == RN - 1)) ? 0.5f : 1.0f;
            sm[P_W + tid] = (tid & 1) ? -wj : wj;
        }
        __syncthreads();
        float a = sm[P_MSC + 0];
        for (int i = tid; i < RN * RN; i += NTHR) {
            float d = sm[P_S + i / RN] - sm[P_S + i % RN];
            sm[P_K + i] = expf(a * d * d);
        }
        __syncthreads();
    }

    // ================= phase 2: stage A (atomic accumulate into g_A) =================
    {
        float* Lt   = sm + SCR;
        float* co_s = sm + SCR + 3096;
        float* invd = sm + SCR + 12312;
        const int b = bid >> 4, n0 = (bid & 15) * 128;

        if (tid < 128) {
            float x = ci[(n0 + tid) * BDIM + b];
            float den = 0.0f;
            #pragma unroll 8
            for (int j = 0; j < RN; ++j) {
                float d = x - sm[P_S + j];
                if (d == 0.0f) d = 1e-30f;
                float r = __fdividef(sm[P_W + j], d);
                den += r;
                Lt[j * 129 + tid] = r;
            }
            invd[tid] = __fdividef(1.0f, den);
        } else {
            for (int i = tid - 128; i < 128 * 18; i += 128) {
                int nn = i / 18, c4 = i - nn * 18;
                float4 v;
                if (c4 < 16)
                    v = ((const float4*)(co + ((size_t)(n0 + nn) * BDIM + b) * CO))[c4];
                else if (c4 == 16)
                    v = make_float4(1.f, 0.f, 0.f, 0.f);
                else
                    v = make_float4(0.f, 0.f, 0.f, 0.f);
                ((float4*)co_s)[nn * 18 + c4] = v;
            }
        }
        __syncthreads();

        if (tid < 216) {
            const int g = tid / 24, q = tid - g * 24;
            float4 acc0 = make_float4(0.f, 0.f, 0.f, 0.f);
            float4 acc1 = make_float4(0.f, 0.f, 0.f, 0.f);
            const float4* co4 = (const float4*)co_s;
            #pragma unroll 4
            for (int n = 0; n < 128; ++n) {
                float k = Lt[q * 129 + n] * invd[n];
                float4 x0 = co4[n * 18 + g * 2];
                float4 x1 = co4[n * 18 + g * 2 + 1];
                acc0.x = fmaf(k, x0.x, acc0.x); acc0.y = fmaf(k, x0.y, acc0.y);
                acc0.z = fmaf(k, x0.z, acc0.z); acc0.w = fmaf(k, x0.w, acc0.w);
                acc1.x = fmaf(k, x1.x, acc1.x); acc1.y = fmaf(k, x1.y, acc1.y);
                acc1.z = fmaf(k, x1.z, acc1.z); acc1.w = fmaf(k, x1.w, acc1.w);
            }
            float* ap = g_A + ((size_t)b * RN + q) * CC + g * 8;
            atomicAdd(ap + 0, acc0.x); atomicAdd(ap + 1, acc0.y);
            atomicAdd(ap + 2, acc0.z); atomicAdd(ap + 3, acc0.w);
            atomicAdd(ap + 4, acc1.x); atomicAdd(ap + 5, acc1.y);
            atomicAdd(ap + 6, acc1.z); atomicAdd(ap + 7, acc1.w);
        }
    }
    grid_barrier();

    // ================= phase 3: stage B  (Bt = K*A ; WB slice = Bt*W^T) =================
    {
        float* As = sm + SCR;
        float* Bt = sm + SCR + 1728;
        float* Ws = sm + SCR + 3456;
        const int b = bid >> 4, r0 = (bid & 15) * 8;

        for (int i = tid; i < RN * CC / 4; i += NTHR)
            ((float4*)As)[i] = __ldcg(((const float4*)(g_A + (size_t)b * RN * CC)) + i);
        for (int i = tid; i < 8 * 65; i += NTHR)
            Ws[i] = W[r0 * 65 + i];
        __syncthreads();

        for (int i = tid; i < RN * CC; i += NTHR) {
            int p = i / CC, c = i - p * CC;
            float acc = 0.0f;
            #pragma unroll 8
            for (int qq = 0; qq < RN; ++qq)
                acc = fmaf(sm[P_K + p * RN + qq], As[qq * CC + c], acc);
            Bt[i] = acc;
            if (c == 64 && r0 == 0) g_Btd[b * RN + p] = acc;
        }
        __syncthreads();

        for (int i = tid; i < RN * 8; i += NTHR) {
            int p = i >> 3, rr = i & 7;
            float acc = 0.0f;
            #pragma unroll 8
            for (int c = 0; c < 64; ++c)
                acc = fmaf(Ws[rr * 65 + (c + 1)], Bt[p * CC + c], acc);
            g_WB[((size_t)b * RN + p) * RDIM + r0 + rr] = acc;
        }
    }
    grid_barrier();

    // ================= phase 4: stage C (2 tiles per block) =================
    float* Lat  = sm + SCR;
    float* WBs  = sm + SCR + 3168;
    float* dens = sm + SCR + 6240;
    float* Btd  = sm + SCR + 6368;
    float* W0s  = sm + SCR + 6392;
    float* bi_s = sm + SCR + 6520;

    for (int t = 0; t < 2; ++t) {
        const int tile = bid + NBLK * t;
        const int b = tile >> 5, m0 = (tile & 31) * 128;
        __syncthreads();   // protect smem reuse across phases/tiles

        for (int i = tid; i < RN * RDIM / 4; i += NTHR)
            ((float4*)WBs)[i] = __ldcg(((const float4*)(g_WB + (size_t)b * RN * RDIM)) + i);
        if (tid < RN) Btd[tid] = __ldcg(&g_Btd[b * RN + tid]);
        if (tid < 128) {
            W0s[tid]  = W[tid * 65];
            bi_s[tid] = bias[tid];
        }
        __syncthreads();

        if (tid < 128) {
            float x = ti[(m0 + tid) * BDIM + b];
            float den = 0.0f;
            #pragma unroll 8
            for (int j = 0; j < RN; ++j) {
                float d = x - sm[P_S + j];
                if (d == 0.0f) d = 1e-30f;
                float r = __fdividef(sm[P_W + j], d);
                den += r;
                Lat[j * 132 + tid] = r;
            }
            float inv = __fdividef(1.0f, den);
            float dm = 0.0f;
            #pragma unroll 8
            for (int j = 0; j < RN; ++j) {
                float v = Lat[j * 132 + tid] * inv;
                Lat[j * 132 + tid] = v;
                dm = fmaf(v, Btd[j], dm);
            }
            dens[tid] = dm;
        }
        __syncthreads();

        const int tx = tid & 15, ty = tid >> 4;
        const int mi = tx * 8, ri = ty * 8;
        float acc[8][8];
        #pragma unroll
        for (int k = 0; k < 8; ++k)
            #pragma unroll
            for (int j = 0; j < 8; ++j) acc[k][j] = 0.0f;

        const float4* Lat4 = (const float4*)Lat;
        const float4* WBs4 = (const float4*)WBs;
        #pragma unroll 4
        for (int p = 0; p < RN; ++p) {
            float4 a0 = Lat4[p * 33 + tx * 2];
            float4 a1 = Lat4[p * 33 + tx * 2 + 1];
            float4 b0 = WBs4[p * 32 + ty * 2];
            float4 b1 = WBs4[p * 32 + ty * 2 + 1];
            float am[8] = {a0.x, a0.y, a0.z, a0.w, a1.x, a1.y, a1.z, a1.w};
            float br[8] = {b0.x, b0.y, b0.z, b0.w, b1.x, b1.y, b1.z, b1.w};
            #pragma unroll
            for (int k = 0; k < 8; ++k)
                #pragma unroll
                for (int j = 0; j < 8; ++j)
                    acc[k][j] = fmaf(am[k], br[j], acc[k][j]);
        }

        float w0[8], bi[8];
        #pragma unroll
        for (int j = 0; j < 8; ++j) { w0[j] = W0s[ri + j]; bi[j] = bi_s[ri + j]; }
        #pragma unroll
        for (int k = 0; k < 8; ++k) {
            float dm = dens[mi + k];
            float inv = __fdividef(1.0f, dm + 1e-8f);
            float o[8];
            #pragma unroll
            for (int j = 0; j < 8; ++j)
                o[j] = fmaf(acc[k][j], inv, fmaf(w0[j], dm, bi[j]));
            float* op = out + ((size_t)(m0 + mi + k) * BDIM + b) * RDIM + ri;
            ((float4*)op)[0] = make_float4(o[0], o[1], o[2], o[3]);
            ((float4*)op)[1] = make_float4(o[4], o[5], o[6], o[7]);
        }
    }
}

// ---------------- launch ----------------
extern "C" void kernel_launch(void* const* d_in, const int* in_sizes, int n_in,
                              void* d_out, int out_size)
{
    const float* ci   = (const float*)d_in[0];
    const float* co   = (const float*)d_in[1];
    const float* ti   = (const float*)d_in[2];
    const float* ls   = (const float*)d_in[3];
    const float* W    = (const float*)d_in[4];
    const float* bias = (const float*)d_in[5];
    float* out = (float*)d_out;

    const int N = in_sizes[0] / BDIM;   // 2048
    const int M = in_sizes[2] / BDIM;   // 4096

    cudaFuncSetAttribute(k_all, cudaFuncAttributeMaxDynamicSharedMemorySize,
                         SM_FLOATS * 4);

    void *p_lo, *p_hi, *p_A, *p_cnt, *p_gen;
    cudaGetSymbolAddress(&p_lo,  g_lo_u);
    cudaGetSymbolAddress(&p_hi,  g_hi_u);
    cudaGetSymbolAddress(&p_A,   g_A);
    cudaGetSymbolAddress(&p_cnt, (const void*)&g_bar_cnt);
    cudaGetSymbolAddress(&p_gen, (const void*)&g_bar_gen);
    cudaMemsetAsync(p_lo,  0xFF, 4);
    cudaMemsetAsync(p_hi,  0x00, 4);
    cudaMemsetAsync(p_cnt, 0x00, 4);
    cudaMemsetAsync(p_gen, 0x00, 4);
    cudaMemsetAsync(p_A,   0x00, BDIM * RN * CC * sizeof(float));

    k_all<<<NBLK, NTHR, SM_FLOATS * 4>>>(ci, co, ti, ls, W, bias, out, N, M);
}